// round 4
// baseline (speedup 1.0000x reference)
#include <cuda_runtime.h>
#include <math.h>
#include <float.h>

#define BB 8
#define CC 128
#define SS 32768
#define NTOK (BB*SS)            // 262144
#define EE 512
#define MARGIN 1.0e-3f

#define OUT_Q_OFF 1LL
#define PERP_OFF  (1LL + (long long)BB*CC*SS)   // 33554433
#define ENC_OFF   (PERP_OFF + 1LL)              // 33554434

// ---------------- scratch (device globals) ----------------------------------
__device__ float        g_sww[EE];       // fl(||w_e||^2), correctly rounded
__device__ unsigned int g_counts[EE];
__device__ double       g_sse;
__device__ int          g_idx[NTOK];
__device__ int          g_amb[NTOK];
__device__ int          g_amb_count;

__device__ __forceinline__ float to_tf32(float x) {
    float r;
    asm("cvt.rna.tf32.f32 %0, %1;" : "=f"(r) : "f"(x));
    return r;
}

// ---------------- prep: sww (double -> fp32) + zero accumulators ------------
__global__ void prep_kernel(const float* __restrict__ w) {
    int gw   = (blockIdx.x * blockDim.x + threadIdx.x) >> 5;
    int lane = threadIdx.x & 31;
    if (gw < EE) {
        const float* wr = w + gw * CC;
        double s = 0.0;
#pragma unroll
        for (int j = 0; j < 4; j++) {
            float v = wr[lane * 4 + j];
            s += (double)v * (double)v;
        }
#pragma unroll
        for (int off = 16; off; off >>= 1)
            s += __shfl_down_sync(0xFFFFFFFFu, s, off);
        if (lane == 0) g_sww[gw] = (float)s;
    }
    if (blockIdx.x == 0 && threadIdx.x < EE) g_counts[threadIdx.x] = 0u;
    if (blockIdx.x == 0 && threadIdx.x == 0) { g_sse = 0.0; g_amb_count = 0; }
}

// ---------------- pass 1: TF32 tensor-core GEMM + top-2 ---------------------
// block: 256 thr (8 warps: 4 in M x 2 in N). Tile: 128 tokens x 512 codes,
// N streamed in 64-code chunks. smem X[128][132] tf32, Wchunk[64][132] tf32.
#define TM 128
#define XS_STRIDE 132
#define WSS 132
#define SMEM_P1 ((TM*XS_STRIDE + 64*WSS) * 4)   // 101376 bytes

extern __shared__ float sdyn[];

__device__ __forceinline__ void mma_tf32(float c[4], const unsigned a[4], const unsigned b[2]) {
    asm volatile(
        "mma.sync.aligned.m16n8k8.row.col.f32.tf32.tf32.f32 "
        "{%0,%1,%2,%3}, {%4,%5,%6,%7}, {%8,%9}, {%0,%1,%2,%3};"
        : "+f"(c[0]), "+f"(c[1]), "+f"(c[2]), "+f"(c[3])
        : "r"(a[0]), "r"(a[1]), "r"(a[2]), "r"(a[3]), "r"(b[0]), "r"(b[1]));
}

__global__ __launch_bounds__(256, 2) void pass1_kernel(const float* __restrict__ x,
                                                       const float* __restrict__ w) {
    float* xs = sdyn;                    // [128][132]
    float* ws = sdyn + TM * XS_STRIDE;   // [64][132]
    __shared__ float s_sww[EE];

    const int b   = blockIdx.x >> 8;
    const int s0  = (blockIdx.x & 255) << 7;
    const int tid = threadIdx.x;
    const int wid = tid >> 5, lane = tid & 31;
    const int l4 = lane >> 2, l2 = lane & 3;
    const int warpM = wid & 3;           // 0..3 -> 32-token slab
    const int warpN = wid >> 2;          // 0..1 -> 32-code half of chunk

    const float* xb = x + ((long long)b * CC) * SS + s0;
    for (int i = tid; i < CC * TM; i += 256) {
        int k = i >> 7, t = i & 127;
        xs[t * XS_STRIDE + k] = to_tf32(xb[(long long)k * SS + t]);
    }
    for (int i = tid; i < EE; i += 256) s_sww[i] = g_sww[i];

    // per-thread top-2 for 4 token rows: r -> token warpM*32 + (r&1)*8 + (r>>1)*16 + l4
    float m1[4], m2[4]; int i1[4];
#pragma unroll
    for (int r = 0; r < 4; r++) { m1[r] = FLT_MAX; m2[r] = FLT_MAX; i1[r] = 0x7FFFFFFF; }

    for (int cc = 0; cc < EE; cc += 64) {
        __syncthreads();
        for (int i = tid; i < 64 * CC; i += 256) {
            int code = i >> 7, k = i & 127;
            ws[code * WSS + k] = to_tf32(w[(cc + code) * CC + k]);
        }
        __syncthreads();

        float acc[2][4][4];
#pragma unroll
        for (int mt = 0; mt < 2; mt++)
#pragma unroll
            for (int nt = 0; nt < 4; nt++)
#pragma unroll
                for (int v = 0; v < 4; v++) acc[mt][nt][v] = 0.f;

        const float* xsw = xs + (warpM * 32) * XS_STRIDE;
        const float* wsw = ws + (warpN * 32) * WSS;

#pragma unroll
        for (int k0 = 0; k0 < CC; k0 += 8) {
            unsigned a[2][4], bf[4][2];
#pragma unroll
            for (int mt = 0; mt < 2; mt++) {
                const float* base = xsw + (mt * 16) * XS_STRIDE + k0 + l2;
                a[mt][0] = __float_as_uint(base[l4 * XS_STRIDE]);
                a[mt][1] = __float_as_uint(base[(l4 + 8) * XS_STRIDE]);
                a[mt][2] = __float_as_uint(base[l4 * XS_STRIDE + 4]);
                a[mt][3] = __float_as_uint(base[(l4 + 8) * XS_STRIDE + 4]);
            }
#pragma unroll
            for (int nt = 0; nt < 4; nt++) {
                const float* base = wsw + (nt * 8 + l4) * WSS + k0 + l2;
                bf[nt][0] = __float_as_uint(base[0]);
                bf[nt][1] = __float_as_uint(base[4]);
            }
#pragma unroll
            for (int mt = 0; mt < 2; mt++)
#pragma unroll
                for (int nt = 0; nt < 4; nt++)
                    mma_tf32(acc[mt][nt], a[mt], bf[nt]);
        }

        // scores + top-2 update (codes visited in ascending order)
#pragma unroll
        for (int nt = 0; nt < 4; nt++) {
            int cb = cc + warpN * 32 + nt * 8 + 2 * l2;
            float sw0 = s_sww[cb], sw1 = s_sww[cb + 1];
#pragma unroll
            for (int mt = 0; mt < 2; mt++) {
#pragma unroll
                for (int half = 0; half < 2; half++) {     // row l4 / l4+8
                    int r = mt * 2 + half;
                    float sc0 = fmaf(-2.f, acc[mt][nt][half * 2 + 0], sw0);
                    float sc1 = fmaf(-2.f, acc[mt][nt][half * 2 + 1], sw1);
                    if (sc0 < m1[r]) { m2[r] = m1[r]; m1[r] = sc0; i1[r] = cb; }
                    else m2[r] = fminf(m2[r], sc0);
                    if (sc1 < m1[r]) { m2[r] = m1[r]; m1[r] = sc1; i1[r] = cb + 1; }
                    else m2[r] = fminf(m2[r], sc1);
                }
            }
        }
    }

    // intra-quad reduce (lanes sharing l4 hold same rows, disjoint codes)
#pragma unroll
    for (int off = 1; off <= 2; off <<= 1) {
#pragma unroll
        for (int r = 0; r < 4; r++) {
            float om1 = __shfl_xor_sync(0xFFFFFFFFu, m1[r], off);
            float om2 = __shfl_xor_sync(0xFFFFFFFFu, m2[r], off);
            int   oi  = __shfl_xor_sync(0xFFFFFFFFu, i1[r], off);
            if (om1 < m1[r] || (om1 == m1[r] && oi < i1[r])) {
                m2[r] = fminf(m1[r], om2);
                m1[r] = om1; i1[r] = oi;
            } else {
                m2[r] = fminf(m2[r], om1);
            }
        }
    }

    // cross-warp (the 2 N-warps share tokens) via smem; reuse ws region
    __syncthreads();
    float* rm1 = ws;               // [2][128]
    float* rm2 = ws + 256;         // [2][128]
    int*   ri  = (int*)(ws + 512); // [2][128]
    if (l2 == 0) {
#pragma unroll
        for (int r = 0; r < 4; r++) {
            int tloc = warpM * 32 + (r >> 1) * 16 + (r & 1) * 8 + l4;
            rm1[warpN * 128 + tloc] = m1[r];
            rm2[warpN * 128 + tloc] = m2[r];
            ri [warpN * 128 + tloc] = i1[r];
        }
    }
    __syncthreads();

    if (tid < TM) {
        float a1 = rm1[tid],      a2 = rm2[tid];      int ai = ri[tid];
        float b1 = rm1[128 + tid], b2 = rm2[128 + tid]; int bi2 = ri[128 + tid];
        float f1, f2; int fi;
        if (b1 < a1 || (b1 == a1 && bi2 < ai)) { f1 = b1; fi = bi2; f2 = fminf(a1, b2); }
        else                                   { f1 = a1; fi = ai;  f2 = fminf(a2, b1); }
        int token = b * SS + s0 + tid;
        g_idx[token] = fi;
        if (f2 - f1 < MARGIN) {
            int p = atomicAdd(&g_amb_count, 1);
            g_amb[p] = token;
        }
    }
}

// ---------------- pass 2: exact rescan (compensated fp32 Dot2) --------------
// d_e = fl( fl(sxx + sww_e) - 2*m_e ),  m_e faithful-rounded via Dot2.
__global__ __launch_bounds__(256) void pass2_kernel(const float* __restrict__ x,
                                                    const float* __restrict__ w) {
    __shared__ float xs_s[8][128];
    const int wid = threadIdx.x >> 5, lane = threadIdx.x & 31;
    const int gw = blockIdx.x * 8 + wid;
    const int nW = gridDim.x * 8;
    const int cnt = g_amb_count;

    for (int it = gw; it < cnt; it += nW) {
        int token = g_amb[it];
        int b = token >> 15, s = token & 32767;
        const float* xb = x + ((long long)b * CC) * SS + s;

        double sx = 0.0;
#pragma unroll
        for (int j = 0; j < 4; j++) {
            float v = xb[(long long)(lane * 4 + j) * SS];
            xs_s[wid][lane * 4 + j] = v;
            sx += (double)v * (double)v;
        }
#pragma unroll
        for (int off = 16; off; off >>= 1)
            sx += __shfl_down_sync(0xFFFFFFFFu, sx, off);
        float sxx = (float)__shfl_sync(0xFFFFFFFFu, sx, 0);
        __syncwarp();

        float bd = FLT_MAX; int bi = 0x7FFFFFFF;
        for (int e = lane; e < EE; e += 32) {
            const float* wr = w + e * CC;
            float sacc = 0.f, comp = 0.f;
#pragma unroll 4
            for (int k = 0; k < CC; k++) {
                float xv = xs_s[wid][k], wv = wr[k];
                float p  = __fmul_rn(xv, wv);
                float pe = __fmaf_rn(xv, wv, -p);          // exact product residual
                float t  = __fadd_rn(sacc, p);             // TwoSum
                float z  = __fsub_rn(t, sacc);
                float se = __fadd_rn(__fsub_rn(p, z),
                                     __fsub_rn(sacc, __fsub_rn(t, z)));
                sacc = t;
                comp = __fadd_rn(comp, __fadd_rn(pe, se));
            }
            float m = __fadd_rn(sacc, comp);
            float d = __fsub_rn(__fadd_rn(sxx, g_sww[e]), 2.0f * m);
            if (d < bd) { bd = d; bi = e; }          // ascending e -> first min
        }
#pragma unroll
        for (int off = 16; off; off >>= 1) {
            float od = __shfl_down_sync(0xFFFFFFFFu, bd, off);
            int   oi = __shfl_down_sync(0xFFFFFFFFu, bi, off);
            if (od < bd || (od == bd && oi < bi)) { bd = od; bi = oi; }
        }
        if (lane == 0) g_idx[token] = bi;
        __syncwarp();
    }
}

// ---------------- histogram (post pass-2) -----------------------------------
__global__ __launch_bounds__(512) void hist_kernel() {
    __shared__ unsigned int sh[EE];
    for (int i = threadIdx.x; i < EE; i += 512) sh[i] = 0u;
    __syncthreads();
    for (int n = blockIdx.x * 512 + threadIdx.x; n < NTOK; n += gridDim.x * 512)
        atomicAdd(&sh[g_idx[n]], 1u);
    __syncthreads();
    for (int i = threadIdx.x; i < EE; i += 512) {
        unsigned int h = sh[i];
        if (h) atomicAdd(&g_counts[i], h);
    }
}

// ---------------- out_q (gather + transpose) + fused MSE --------------------
__global__ __launch_bounds__(256) void outq_kernel(const float* __restrict__ x,
                                                   const float* __restrict__ w,
                                                   float* __restrict__ out) {
    __shared__ float qs[64 * 129];
    __shared__ int   idxs[64];
    __shared__ float wsum[8];

    const int b  = blockIdx.x >> 9;
    const int s0 = (blockIdx.x & 511) << 6;
    const int tid = threadIdx.x;

    if (tid < 64) idxs[tid] = g_idx[b * SS + s0 + tid];
    __syncthreads();

    for (int i = tid; i < 64 * CC; i += 256) {
        int t = i >> 7, k = i & 127;
        qs[t * 129 + k] = w[idxs[t] * CC + k];
    }
    __syncthreads();

    const float* xb = x + ((long long)b * CC) * SS + s0;
    float* ob = out + OUT_Q_OFF + ((long long)b * CC) * SS + s0;
    float lsum = 0.f;
    for (int i = tid; i < CC * 64; i += 256) {
        int c = i >> 6, t = i & 63;
        float q = qs[t * 129 + c];
        long long off = (long long)c * SS + t;
        float xv = xb[off];
        ob[off] = q;
        float d = q - xv;
        lsum = fmaf(d, d, lsum);
    }
#pragma unroll
    for (int o = 16; o > 0; o >>= 1)
        lsum += __shfl_down_sync(0xFFFFFFFFu, lsum, o);
    if ((tid & 31) == 0) wsum[tid >> 5] = lsum;
    __syncthreads();
    if (tid == 0) {
        double ssum = 0.0;
#pragma unroll
        for (int i = 0; i < 8; i++) ssum += (double)wsum[i];
        atomicAdd(&g_sse, ssum);
    }
}

// ---------------- one-hot scatter --------------------------------------------
__global__ void scatter_kernel(float* __restrict__ out) {
    int n = blockIdx.x * 256 + threadIdx.x;
    out[ENC_OFF + (long long)n * EE + g_idx[n]] = 1.0f;
}

// ---------------- finalize: loss + perplexity --------------------------------
__global__ void finalize_kernel(float* __restrict__ out) {
    __shared__ double ssum[EE];
    int e = threadIdx.x;
    double p = (double)g_counts[e] / (double)NTOK;
    ssum[e] = p * log(p + 1e-10);
    __syncthreads();
    for (int s = 256; s > 0; s >>= 1) {
        if (e < s) ssum[e] += ssum[e + s];
        __syncthreads();
    }
    if (e == 0) {
        out[PERP_OFF] = (float)exp(-ssum[0]);
        out[0] = (float)(1.25 * g_sse / (double)((long long)NTOK * CC));
    }
}

// ---------------- launch ------------------------------------------------------
extern "C" void kernel_launch(void* const* d_in, const int* in_sizes, int n_in,
                              void* d_out, int out_size) {
    const float* x = (const float*)d_in[0];   // (8,128,32,32,32) fp32
    const float* w = (const float*)d_in[1];   // (512,128) fp32
    float* out = (float*)d_out;

    cudaFuncSetAttribute(pass1_kernel, cudaFuncAttributeMaxDynamicSharedMemorySize,
                         SMEM_P1);

    prep_kernel<<<16, 1024>>>(w);
    cudaMemsetAsync(out + ENC_OFF, 0, (size_t)NTOK * EE * sizeof(float));
    pass1_kernel<<<NTOK / TM, 256, SMEM_P1>>>(x, w);
    pass2_kernel<<<256, 256>>>(x, w);
    hist_kernel<<<512, 512>>>();
    outq_kernel<<<NTOK / 64, 256>>>(x, w, out);
    scatter_kernel<<<NTOK / 256, 256>>>(out);
    finalize_kernel<<<1, EE>>>(out);
}

// round 5
// speedup vs baseline: 3.1259x; 3.1259x over previous
#include <cuda_runtime.h>
#include <math.h>
#include <float.h>

#define BB 8
#define CC 128
#define SS 32768
#define NTOK (BB*SS)            // 262144
#define EE 512
#define MARGIN 1.0e-4f

#define OUT_Q_OFF 1LL
#define PERP_OFF  (1LL + (long long)BB*CC*SS)   // 33554433
#define ENC_OFF   (PERP_OFF + 1LL)              // 33554434

// ---------------- scratch (device globals) ----------------------------------
__device__ float        g_sww[EE];       // fl(||w_e||^2), correctly rounded
__device__ unsigned int g_counts[EE];
__device__ double       g_sse;
__device__ int          g_idx[NTOK];
__device__ int          g_amb[NTOK];
__device__ int          g_amb_count;

// ---------------- prep: sww (double -> fp32) + zero accumulators ------------
__global__ void prep_kernel(const float* __restrict__ w) {
    int gw   = (blockIdx.x * blockDim.x + threadIdx.x) >> 5;
    int lane = threadIdx.x & 31;
    if (gw < EE) {
        const float* wr = w + gw * CC;
        double s = 0.0;
#pragma unroll
        for (int j = 0; j < 4; j++) {
            float v = wr[lane * 4 + j];
            s += (double)v * (double)v;
        }
#pragma unroll
        for (int off = 16; off; off >>= 1)
            s += __shfl_down_sync(0xFFFFFFFFu, s, off);
        if (lane == 0) g_sww[gw] = (float)s;
    }
    if (blockIdx.x == 0 && threadIdx.x < EE) g_counts[threadIdx.x] = 0u;
    if (blockIdx.x == 0 && threadIdx.x == 0) { g_sse = 0.0; g_amb_count = 0; }
}

// ---------------- pass 1: fp32 GEMM (4x8 microtile) + top-2 + fused hist ----
// block: 256 thr as 16(ty) x 16(tx). Tile: 64 tokens x 512 codes in 4 chunks
// of 128 codes. smem: xs[k][t] 128x64, ws[k][c] 128x132 (pad).
#define TM 64
#define NCHUNK 128
#define WSS 132
#define XS_FLOATS (CC*TM)               // 8192
#define SMEM_P1 ((XS_FLOATS + CC*WSS) * 4)   // (8192+16896)*4 = 100352 B

extern __shared__ float sdyn[];

__global__ __launch_bounds__(256, 2) void pass1_kernel(const float* __restrict__ x,
                                                       const float* __restrict__ w) {
    float* xs = sdyn;                 // [128][64]
    float* ws = sdyn + XS_FLOATS;     // [128][132]
    __shared__ float        s_sww[EE];
    __shared__ unsigned int hist[EE];

    const int b   = blockIdx.x >> 9;          // 512 blocks per batch
    const int s0  = (blockIdx.x & 511) << 6;  // *64
    const int tid = threadIdx.x;
    const int ty  = tid >> 4;                 // 0..15 -> 4 tokens
    const int tx  = tid & 15;                 // 0..15 -> 8 codes
    const int t0  = ty * 4;
    const int c0t = tx * 8;

    // load x tile (coalesced) + sww + hist init
    const float* xb = x + ((long long)b * CC) * SS + s0;
    for (int i = tid; i < XS_FLOATS; i += 256) {
        int k = i >> 6, t = i & 63;
        xs[i] = xb[(long long)k * SS + t];
    }
    for (int i = tid; i < EE; i += 256) { s_sww[i] = g_sww[i]; hist[i] = 0u; }

    float m1[4], m2[4]; int i1[4];
#pragma unroll
    for (int r = 0; r < 4; r++) { m1[r] = FLT_MAX; m2[r] = FLT_MAX; i1[r] = 0x7FFFFFFF; }

    for (int cc = 0; cc < EE; cc += NCHUNK) {
        __syncthreads();
        // transpose-load W chunk: ws[k*132 + c] = w[(cc+c)*128 + k]
        for (int i = tid; i < NCHUNK * CC; i += 256) {
            int c = i >> 7, k = i & 127;
            ws[k * WSS + c] = w[(cc + c) * CC + k];
        }
        __syncthreads();

        float acc[4][8];
#pragma unroll
        for (int r = 0; r < 4; r++)
#pragma unroll
            for (int j = 0; j < 8; j++) acc[r][j] = 0.f;

#pragma unroll 8
        for (int k = 0; k < CC; k++) {
            float4 xv = *(const float4*)&xs[k * TM + t0];
            float4 wa = *(const float4*)&ws[k * WSS + c0t];
            float4 wb = *(const float4*)&ws[k * WSS + c0t + 4];
            float xr[4] = {xv.x, xv.y, xv.z, xv.w};
            float wr[8] = {wa.x, wa.y, wa.z, wa.w, wb.x, wb.y, wb.z, wb.w};
#pragma unroll
            for (int r = 0; r < 4; r++)
#pragma unroll
                for (int j = 0; j < 8; j++)
                    acc[r][j] = fmaf(xr[r], wr[j], acc[r][j]);
        }

        // scores + top-2 (codes ascending within thread)
#pragma unroll
        for (int j = 0; j < 8; j++) {
            int c = cc + c0t + j;
            float sw = s_sww[c];
#pragma unroll
            for (int r = 0; r < 4; r++) {
                float sc = fmaf(-2.f, acc[r][j], sw);
                if (sc < m1[r]) { m2[r] = m1[r]; m1[r] = sc; i1[r] = c; }
                else            { m2[r] = fminf(m2[r], sc); }
            }
        }
    }

    // cross-thread reduce: 16 tx-threads share each token; reuse ws
    __syncthreads();
    float* rv1 = ws;                         // [64][16]
    float* rv2 = ws + TM * 16;               // [64][16]
    int*   ri1 = (int*)(ws + TM * 32);       // [64][16]
#pragma unroll
    for (int r = 0; r < 4; r++) {
        int t = t0 + r;
        rv1[t * 16 + tx] = m1[r];
        rv2[t * 16 + tx] = m2[r];
        ri1[t * 16 + tx] = i1[r];
    }
    __syncthreads();

    if (tid < TM) {
        float b1 = FLT_MAX, b2 = FLT_MAX;
        int   bi = 0x7FFFFFFF;
#pragma unroll
        for (int j = 0; j < 16; j++) {
            float v1 = rv1[tid * 16 + j];
            int   ii = ri1[tid * 16 + j];
            float v2 = rv2[tid * 16 + j];
            if (v1 < b1 || (v1 == b1 && ii < bi)) { b2 = fminf(b2, b1); b1 = v1; bi = ii; }
            else b2 = fminf(b2, v1);
            b2 = fminf(b2, v2);
        }
        int token = b * SS + s0 + tid;
        g_idx[token] = bi;
        atomicAdd(&hist[bi], 1u);
        if (b2 - b1 < MARGIN) {
            int p = atomicAdd(&g_amb_count, 1);
            g_amb[p] = token;
        }
    }
    __syncthreads();
    for (int i = tid; i < EE; i += 256) {
        unsigned int h = hist[i];
        if (h) atomicAdd(&g_counts[i], h);
    }
}

// ---------------- pass 2: fp32-exact reference emulation --------------------
// d_e = fl( fl(sxx + sww_e) - 2*m_e ),  m_e correctly rounded via double acc.
// Patches g_counts when it flips an index.
__global__ __launch_bounds__(256) void pass2_kernel(const float* __restrict__ x,
                                                    const float* __restrict__ w) {
    __shared__ float xs_s[8][128];
    const int wid = threadIdx.x >> 5, lane = threadIdx.x & 31;
    const int gw = blockIdx.x * 8 + wid;
    const int nW = gridDim.x * 8;
    const int cnt = g_amb_count;

    for (int it = gw; it < cnt; it += nW) {
        int token = g_amb[it];
        int b = token >> 15, s = token & 32767;
        const float* xb = x + ((long long)b * CC) * SS + s;

        double sx = 0.0;
#pragma unroll
        for (int j = 0; j < 4; j++) {
            float v = xb[(long long)(lane * 4 + j) * SS];
            xs_s[wid][lane * 4 + j] = v;
            sx += (double)v * (double)v;
        }
#pragma unroll
        for (int off = 16; off; off >>= 1)
            sx += __shfl_down_sync(0xFFFFFFFFu, sx, off);
        float sxx = (float)__shfl_sync(0xFFFFFFFFu, sx, 0);
        __syncwarp();

        float bd = FLT_MAX; int bi = 0x7FFFFFFF;
        for (int e = lane; e < EE; e += 32) {
            const float* wr = w + e * CC;
            double a = 0.0;
#pragma unroll 4
            for (int k = 0; k < CC; k++)
                a += (double)xs_s[wid][k] * (double)wr[k];
            float m = (float)a;
            float d = __fsub_rn(__fadd_rn(sxx, g_sww[e]), 2.0f * m);
            if (d < bd) { bd = d; bi = e; }          // ascending e -> first min
        }
#pragma unroll
        for (int off = 16; off; off >>= 1) {
            float od = __shfl_down_sync(0xFFFFFFFFu, bd, off);
            int   oi = __shfl_down_sync(0xFFFFFFFFu, bi, off);
            if (od < bd || (od == bd && oi < bi)) { bd = od; bi = oi; }
        }
        if (lane == 0) {
            int old = g_idx[token];
            if (bi != old) {
                g_idx[token] = bi;
                atomicSub(&g_counts[old], 1u);
                atomicAdd(&g_counts[bi], 1u);
            }
        }
        __syncwarp();
    }
}

// ---------------- out_q (gather + transpose) + fused MSE --------------------
__global__ __launch_bounds__(256) void outq_kernel(const float* __restrict__ x,
                                                   const float* __restrict__ w,
                                                   float* __restrict__ out) {
    __shared__ float qs[64 * 129];
    __shared__ int   idxs[64];
    __shared__ float wsum[8];

    const int b  = blockIdx.x >> 9;
    const int s0 = (blockIdx.x & 511) << 6;
    const int tid = threadIdx.x;

    if (tid < 64) idxs[tid] = g_idx[b * SS + s0 + tid];
    __syncthreads();

    for (int i = tid; i < 64 * CC; i += 256) {
        int t = i >> 7, k = i & 127;
        qs[t * 129 + k] = w[idxs[t] * CC + k];
    }
    __syncthreads();

    const float* xb = x + ((long long)b * CC) * SS + s0;
    float* ob = out + OUT_Q_OFF + ((long long)b * CC) * SS + s0;
    float lsum = 0.f;
    for (int i = tid; i < CC * 64; i += 256) {
        int c = i >> 6, t = i & 63;
        float q = qs[t * 129 + c];
        long long off = (long long)c * SS + t;
        float xv = xb[off];
        ob[off] = q;
        float d = q - xv;
        lsum = fmaf(d, d, lsum);
    }
#pragma unroll
    for (int o = 16; o > 0; o >>= 1)
        lsum += __shfl_down_sync(0xFFFFFFFFu, lsum, o);
    if ((tid & 31) == 0) wsum[tid >> 5] = lsum;
    __syncthreads();
    if (tid == 0) {
        double ssum = 0.0;
#pragma unroll
        for (int i = 0; i < 8; i++) ssum += (double)wsum[i];
        atomicAdd(&g_sse, ssum);
    }
}

// ---------------- one-hot scatter --------------------------------------------
__global__ void scatter_kernel(float* __restrict__ out) {
    int n = blockIdx.x * 256 + threadIdx.x;
    out[ENC_OFF + (long long)n * EE + g_idx[n]] = 1.0f;
}

// ---------------- finalize: loss + perplexity --------------------------------
__global__ void finalize_kernel(float* __restrict__ out) {
    __shared__ double ssum[EE];
    int e = threadIdx.x;
    double p = (double)g_counts[e] / (double)NTOK;
    ssum[e] = p * log(p + 1e-10);
    __syncthreads();
    for (int s = 256; s > 0; s >>= 1) {
        if (e < s) ssum[e] += ssum[e + s];
        __syncthreads();
    }
    if (e == 0) {
        out[PERP_OFF] = (float)exp(-ssum[0]);
        out[0] = (float)(1.25 * g_sse / (double)((long long)NTOK * CC));
    }
}

// ---------------- launch ------------------------------------------------------
extern "C" void kernel_launch(void* const* d_in, const int* in_sizes, int n_in,
                              void* d_out, int out_size) {
    const float* x = (const float*)d_in[0];   // (8,128,32,32,32) fp32
    const float* w = (const float*)d_in[1];   // (512,128) fp32
    float* out = (float*)d_out;

    cudaFuncSetAttribute(pass1_kernel, cudaFuncAttributeMaxDynamicSharedMemorySize,
                         SMEM_P1);

    prep_kernel<<<16, 1024>>>(w);
    cudaMemsetAsync(out + ENC_OFF, 0, (size_t)NTOK * EE * sizeof(float));
    pass1_kernel<<<NTOK / TM, 256, SMEM_P1>>>(x, w);
    pass2_kernel<<<256, 256>>>(x, w);
    outq_kernel<<<NTOK / 64, 256>>>(x, w, out);
    scatter_kernel<<<NTOK / 256, 256>>>(out);
    finalize_kernel<<<1, EE>>>(out);
}

// round 6
// speedup vs baseline: 3.5789x; 1.1449x over previous
#include <cuda_runtime.h>
#include <math.h>
#include <float.h>

#define BB 8
#define CC 128
#define SS 32768
#define NTOK (BB*SS)            // 262144
#define EE 512
#define MARGIN 1.0e-4f

#define OUT_Q_OFF 1LL
#define PERP_OFF  (1LL + (long long)BB*CC*SS)   // 33554433
#define ENC_OFF   (PERP_OFF + 1LL)              // 33554434

// ---------------- scratch (device globals) ----------------------------------
__device__ float        g_sww[EE];       // fl(||w_e||^2), correctly rounded
__device__ unsigned int g_counts[EE];
__device__ double       g_sse;
__device__ int          g_idx[NTOK];
__device__ int          g_amb[NTOK];
__device__ int          g_amb_count;

// ---------------- prep: sww (double -> fp32) + zero accumulators ------------
__global__ void prep_kernel(const float* __restrict__ w) {
    int gw   = (blockIdx.x * blockDim.x + threadIdx.x) >> 5;
    int lane = threadIdx.x & 31;
    if (gw < EE) {
        const float* wr = w + gw * CC;
        double s = 0.0;
#pragma unroll
        for (int j = 0; j < 4; j++) {
            float v = wr[lane * 4 + j];
            s += (double)v * (double)v;
        }
#pragma unroll
        for (int off = 16; off; off >>= 1)
            s += __shfl_down_sync(0xFFFFFFFFu, s, off);
        if (lane == 0) g_sww[gw] = (float)s;
    }
    if (blockIdx.x == 0 && threadIdx.x < EE) g_counts[threadIdx.x] = 0u;
    if (blockIdx.x == 0 && threadIdx.x == 0) { g_sse = 0.0; g_amb_count = 0; }
}

// ---------------- pass 1: fp32 GEMM (8x4 microtile) + top-2 + fused hist ----
// block: 256 thr as 16(ty: 8 tokens) x 16(tx: 4 codes).
// Tile: 128 tokens x 512 codes in 8 chunks of 64 codes.
// smem: xs[k][t] 128x128, ws[k][c] 128x68 (pad).
#define TM 128
#define NCH 64
#define WSS 68
#define XS_FLOATS (CC*TM)                    // 16384
#define SMEM_P1 ((XS_FLOATS + CC*WSS) * 4)   // (16384+8704)*4 = 100352 B

extern __shared__ float sdyn[];

__global__ __launch_bounds__(256, 2) void pass1_kernel(const float* __restrict__ x,
                                                       const float* __restrict__ w) {
    float* xs = sdyn;                 // [128][128] k-major
    float* ws = sdyn + XS_FLOATS;     // [128][68]  k-major, padded
    __shared__ float        s_sww[EE];
    __shared__ unsigned int hist[EE];

    const int b   = blockIdx.x >> 8;          // 256 blocks per batch
    const int s0  = (blockIdx.x & 255) << 7;  // *128
    const int tid = threadIdx.x;
    const int ty  = tid >> 4;                 // 0..15 -> 8 tokens
    const int tx  = tid & 15;                 // 0..15 -> 4 codes
    const int t0  = ty * 8;
    const int c0t = tx * 4;

    // load x tile (coalesced) + sww + hist init
    const float* xb = x + ((long long)b * CC) * SS + s0;
    for (int i = tid; i < XS_FLOATS; i += 256) {
        int k = i >> 7, t = i & 127;
        xs[i] = xb[(long long)k * SS + t];
    }
    for (int i = tid; i < EE; i += 256) { s_sww[i] = g_sww[i]; hist[i] = 0u; }

    float m1[8], m2[8]; int i1[8];
#pragma unroll
    for (int r = 0; r < 8; r++) { m1[r] = FLT_MAX; m2[r] = FLT_MAX; i1[r] = 0x7FFFFFFF; }

    for (int cc = 0; cc < EE; cc += NCH) {
        __syncthreads();
        // transpose-load W chunk: ws[k*68 + c] = w[(cc+c)*128 + k]
        for (int i = tid; i < NCH * CC; i += 256) {
            int c = i >> 7, k = i & 127;
            ws[k * WSS + c] = w[(cc + c) * CC + k];
        }
        __syncthreads();

        float acc[8][4];
#pragma unroll
        for (int r = 0; r < 8; r++)
#pragma unroll
            for (int j = 0; j < 4; j++) acc[r][j] = 0.f;

#pragma unroll 4
        for (int k = 0; k < CC; k++) {
            float4 xa = *(const float4*)&xs[k * TM + t0];
            float4 xv = *(const float4*)&xs[k * TM + t0 + 4];
            float4 wv = *(const float4*)&ws[k * WSS + c0t];
            float xr[8] = {xa.x, xa.y, xa.z, xa.w, xv.x, xv.y, xv.z, xv.w};
            float wr[4] = {wv.x, wv.y, wv.z, wv.w};
#pragma unroll
            for (int r = 0; r < 8; r++)
#pragma unroll
                for (int j = 0; j < 4; j++)
                    acc[r][j] = fmaf(xr[r], wr[j], acc[r][j]);
        }

        // scores + top-2 (codes ascending within thread)
#pragma unroll
        for (int j = 0; j < 4; j++) {
            int c = cc + c0t + j;
            float sw = s_sww[c];
#pragma unroll
            for (int r = 0; r < 8; r++) {
                float sc = fmaf(-2.f, acc[r][j], sw);
                if (sc < m1[r]) { m2[r] = m1[r]; m1[r] = sc; i1[r] = c; }
                else            { m2[r] = fminf(m2[r], sc); }
            }
        }
    }

    // cross-thread reduce: 16 tx-threads share each token; reuse xs
    __syncthreads();
    float* rv1 = xs;                          // [128][16]
    float* rv2 = xs + TM * 16;                // [128][16]
    int*   ri1 = (int*)(xs + TM * 32);        // [128][16]
#pragma unroll
    for (int r = 0; r < 8; r++) {
        int t = t0 + r;
        rv1[t * 16 + tx] = m1[r];
        rv2[t * 16 + tx] = m2[r];
        ri1[t * 16 + tx] = i1[r];
    }
    __syncthreads();

    if (tid < TM) {
        float b1 = FLT_MAX, b2 = FLT_MAX;
        int   bi = 0x7FFFFFFF;
#pragma unroll
        for (int j = 0; j < 16; j++) {
            float v1 = rv1[tid * 16 + j];
            int   ii = ri1[tid * 16 + j];
            float v2 = rv2[tid * 16 + j];
            if (v1 < b1 || (v1 == b1 && ii < bi)) { b2 = fminf(b2, b1); b1 = v1; bi = ii; }
            else b2 = fminf(b2, v1);
            b2 = fminf(b2, v2);
        }
        int token = b * SS + s0 + tid;
        g_idx[token] = bi;
        atomicAdd(&hist[bi], 1u);
        if (b2 - b1 < MARGIN) {
            int p = atomicAdd(&g_amb_count, 1);
            g_amb[p] = token;
        }
    }
    __syncthreads();
    for (int i = tid; i < EE; i += 256) {
        unsigned int h = hist[i];
        if (h) atomicAdd(&g_counts[i], h);
    }
}

// ---------------- pass 2: fp32-exact reference emulation --------------------
// d_e = fl( fl(sxx + sww_e) - 2*m_e ),  m_e correctly rounded via double acc.
// Patches g_counts when it flips an index.
__global__ __launch_bounds__(256) void pass2_kernel(const float* __restrict__ x,
                                                    const float* __restrict__ w) {
    __shared__ float xs_s[8][128];
    const int wid = threadIdx.x >> 5, lane = threadIdx.x & 31;
    const int gw = blockIdx.x * 8 + wid;
    const int nW = gridDim.x * 8;
    const int cnt = g_amb_count;

    for (int it = gw; it < cnt; it += nW) {
        int token = g_amb[it];
        int b = token >> 15, s = token & 32767;
        const float* xb = x + ((long long)b * CC) * SS + s;

        double sx = 0.0;
#pragma unroll
        for (int j = 0; j < 4; j++) {
            float v = xb[(long long)(lane * 4 + j) * SS];
            xs_s[wid][lane * 4 + j] = v;
            sx += (double)v * (double)v;
        }
#pragma unroll
        for (int off = 16; off; off >>= 1)
            sx += __shfl_down_sync(0xFFFFFFFFu, sx, off);
        float sxx = (float)__shfl_sync(0xFFFFFFFFu, sx, 0);
        __syncwarp();

        float bd = FLT_MAX; int bi = 0x7FFFFFFF;
        for (int e = lane; e < EE; e += 32) {
            const float* wr = w + e * CC;
            double a = 0.0;
#pragma unroll 4
            for (int k = 0; k < CC; k++)
                a += (double)xs_s[wid][k] * (double)wr[k];
            float m = (float)a;
            float d = __fsub_rn(__fadd_rn(sxx, g_sww[e]), 2.0f * m);
            if (d < bd) { bd = d; bi = e; }          // ascending e -> first min
        }
#pragma unroll
        for (int off = 16; off; off >>= 1) {
            float od = __shfl_down_sync(0xFFFFFFFFu, bd, off);
            int   oi = __shfl_down_sync(0xFFFFFFFFu, bi, off);
            if (od < bd || (od == bd && oi < bi)) { bd = od; bi = oi; }
        }
        if (lane == 0) {
            int old = g_idx[token];
            if (bi != old) {
                g_idx[token] = bi;
                atomicSub(&g_counts[old], 1u);
                atomicAdd(&g_counts[bi], 1u);
            }
        }
        __syncwarp();
    }
}

// ---------------- encodings: fused zero-fill + one-hot ----------------------
// float2 stores (ENC_OFF is 8B-aligned, not 16B).
__global__ __launch_bounds__(256) void encfill_kernel(float* __restrict__ out) {
    float2* enc = (float2*)(out + ENC_OFF);
    const long long total = (long long)NTOK * (EE / 2);
    long long stride = (long long)gridDim.x * blockDim.x;
    for (long long i = (long long)blockIdx.x * blockDim.x + threadIdx.x;
         i < total; i += stride) {
        int token = (int)(i >> 8);            // 256 float2 per token
        int q     = (int)(i & 255);
        int idx   = g_idx[token];
        float2 v = make_float2(0.f, 0.f);
        if (q == (idx >> 1)) { if (idx & 1) v.y = 1.f; else v.x = 1.f; }
        enc[i] = v;
    }
}

// ---------------- out_q (gather + transpose) + fused MSE --------------------
__global__ __launch_bounds__(256) void outq_kernel(const float* __restrict__ x,
                                                   const float* __restrict__ w,
                                                   float* __restrict__ out) {
    __shared__ float qs[64 * 129];
    __shared__ int   idxs[64];
    __shared__ float wsum[8];

    const int b  = blockIdx.x >> 9;
    const int s0 = (blockIdx.x & 511) << 6;
    const int tid = threadIdx.x;

    if (tid < 64) idxs[tid] = g_idx[b * SS + s0 + tid];
    __syncthreads();

    for (int i = tid; i < 64 * CC; i += 256) {
        int t = i >> 7, k = i & 127;
        qs[t * 129 + k] = w[idxs[t] * CC + k];
    }
    __syncthreads();

    const float* xb = x + ((long long)b * CC) * SS + s0;
    float* ob = out + OUT_Q_OFF + ((long long)b * CC) * SS + s0;
    float lsum = 0.f;
    for (int i = tid; i < CC * 64; i += 256) {
        int c = i >> 6, t = i & 63;
        float q = qs[t * 129 + c];
        long long off = (long long)c * SS + t;
        float xv = xb[off];
        ob[off] = q;
        float d = q - xv;
        lsum = fmaf(d, d, lsum);
    }
#pragma unroll
    for (int o = 16; o > 0; o >>= 1)
        lsum += __shfl_down_sync(0xFFFFFFFFu, lsum, o);
    if ((tid & 31) == 0) wsum[tid >> 5] = lsum;
    __syncthreads();
    if (tid == 0) {
        double ssum = 0.0;
#pragma unroll
        for (int i = 0; i < 8; i++) ssum += (double)wsum[i];
        atomicAdd(&g_sse, ssum);
    }
}

// ---------------- finalize: loss + perplexity --------------------------------
__global__ void finalize_kernel(float* __restrict__ out) {
    __shared__ double ssum[EE];
    int e = threadIdx.x;
    double p = (double)g_counts[e] / (double)NTOK;
    ssum[e] = p * log(p + 1e-10);
    __syncthreads();
    for (int s = 256; s > 0; s >>= 1) {
        if (e < s) ssum[e] += ssum[e + s];
        __syncthreads();
    }
    if (e == 0) {
        out[PERP_OFF] = (float)exp(-ssum[0]);
        out[0] = (float)(1.25 * g_sse / (double)((long long)NTOK * CC));
    }
}

// ---------------- launch ------------------------------------------------------
extern "C" void kernel_launch(void* const* d_in, const int* in_sizes, int n_in,
                              void* d_out, int out_size) {
    const float* x = (const float*)d_in[0];   // (8,128,32,32,32) fp32
    const float* w = (const float*)d_in[1];   // (512,128) fp32
    float* out = (float*)d_out;

    cudaFuncSetAttribute(pass1_kernel, cudaFuncAttributeMaxDynamicSharedMemorySize,
                         SMEM_P1);

    prep_kernel<<<16, 1024>>>(w);
    pass1_kernel<<<NTOK / TM, 256, SMEM_P1>>>(x, w);
    pass2_kernel<<<256, 256>>>(x, w);
    encfill_kernel<<<2048, 256>>>(out);
    outq_kernel<<<NTOK / 64, 256>>>(x, w, out);
    finalize_kernel<<<1, EE>>>(out);
}